// round 2
// baseline (speedup 1.0000x reference)
#include <cuda_runtime.h>

// MultiGrid multi-resolution trilinear sampling with smoothstep weights.
// vols: [1, 4, D, H, W] float32, channel-major. grid: [1,1,1,N,3] in [-1,1].
// out:  [1, 16, 1, 1, N]  -> out[(vol*4 + c)*N + i]
//
// Direct-gather baseline: 1 thread per point, all 4 volumes.

#define NCH 4

template<int D, int H, int W>
__device__ __forceinline__ void sample_vol(const float* __restrict__ vol,
                                           float gx, float gy, float gz,
                                           float r[NCH])
{
    // align_corners=True mapping with border clamp
    float x = fminf(fmaxf((gx + 1.0f) * (0.5f * (float)(W - 1)), 0.0f), (float)(W - 1));
    float y = fminf(fmaxf((gy + 1.0f) * (0.5f * (float)(H - 1)), 0.0f), (float)(H - 1));
    float z = fminf(fmaxf((gz + 1.0f) * (0.5f * (float)(D - 1)), 0.0f), (float)(D - 1));

    float x0f = floorf(x), y0f = floorf(y), z0f = floorf(z);
    float tx = x - x0f, ty = y - y0f, tz = z - z0f;

    // smoothstep
    tx = tx * tx * (3.0f - 2.0f * tx);
    ty = ty * ty * (3.0f - 2.0f * ty);
    tz = tz * tz * (3.0f - 2.0f * tz);

    int x0 = (int)x0f, y0 = (int)y0f, z0 = (int)z0f;
    // clamped +1 neighbors folded into address deltas
    int dx = (x0 < W - 1) ? 1     : 0;
    int dy = (y0 < H - 1) ? W     : 0;
    int dz = (z0 < D - 1) ? H * W : 0;

    int base = (z0 * H + y0) * W + x0;
    const int S = D * H * W;   // channel stride

    #pragma unroll
    for (int c = 0; c < NCH; c++) {
        const float* p = vol + c * S + base;
        // issue all 8 gathers before the lerp tree (MLP)
        float c000 = __ldg(p);
        float c001 = __ldg(p + dx);
        float c010 = __ldg(p + dy);
        float c011 = __ldg(p + dy + dx);
        float c100 = __ldg(p + dz);
        float c101 = __ldg(p + dz + dx);
        float c110 = __ldg(p + dz + dy);
        float c111 = __ldg(p + dz + dy + dx);

        float c00 = fmaf(c001 - c000, tx, c000);
        float c01 = fmaf(c011 - c010, tx, c010);
        float c10 = fmaf(c101 - c100, tx, c100);
        float c11 = fmaf(c111 - c110, tx, c110);

        float c0 = fmaf(c01 - c00, ty, c00);
        float c1 = fmaf(c11 - c10, ty, c10);

        r[c] = fmaf(c1 - c0, tz, c0);
    }
}

__global__ void __launch_bounds__(256)
multigrid_kernel(const float* __restrict__ grid,
                 const float* __restrict__ v0,
                 const float* __restrict__ v1,
                 const float* __restrict__ v2,
                 const float* __restrict__ v3,
                 float* __restrict__ out,
                 int N)
{
    int i = blockIdx.x * blockDim.x + threadIdx.x;
    if (i >= N) return;

    float gx = __ldg(grid + 3 * i + 0);
    float gy = __ldg(grid + 3 * i + 1);
    float gz = __ldg(grid + 3 * i + 2);

    float r0[NCH], r1[NCH], r2[NCH], r3[NCH];
    sample_vol< 32,  32,  32>(v0, gx, gy, gz, r0);
    sample_vol< 64,  64,  64>(v1, gx, gy, gz, r1);
    sample_vol<128, 128, 128>(v2, gx, gy, gz, r2);
    sample_vol<256, 256, 256>(v3, gx, gy, gz, r3);

    #pragma unroll
    for (int c = 0; c < NCH; c++) out[(0 * NCH + c) * N + i] = r0[c];
    #pragma unroll
    for (int c = 0; c < NCH; c++) out[(1 * NCH + c) * N + i] = r1[c];
    #pragma unroll
    for (int c = 0; c < NCH; c++) out[(2 * NCH + c) * N + i] = r2[c];
    #pragma unroll
    for (int c = 0; c < NCH; c++) out[(3 * NCH + c) * N + i] = r3[c];
}

extern "C" void kernel_launch(void* const* d_in, const int* in_sizes, int n_in,
                              void* d_out, int out_size)
{
    const float* grid = (const float*)d_in[0];
    const float* v0   = (const float*)d_in[1];
    const float* v1   = (const float*)d_in[2];
    const float* v2   = (const float*)d_in[3];
    const float* v3   = (const float*)d_in[4];
    float* out        = (float*)d_out;

    int N = in_sizes[0] / 3;   // grid has N*3 elements

    int threads = 256;
    int blocks  = (N + threads - 1) / threads;
    multigrid_kernel<<<blocks, threads>>>(grid, v0, v1, v2, v3, out, N);
}

// round 8
// speedup vs baseline: 2.4125x; 2.4125x over previous
#include <cuda_runtime.h>
#include <cuda_fp16.h>

// MultiGrid multires trilinear sampling, smoothstep weights, align_corners.
// Strategy: per launch, repack each volume [4,D,H,W] fp32 -> [D,H,W,4] fp16
// (half4 = 8B per voxel) in __device__ scratch, then gather with one 8B load
// per corner (all 4 channels at once). Cuts DRAM+L2 sector traffic ~4-8x vs
// channel-major fp32 gathers.
//
// All kernels reference the __device__ scratch symbols directly: kernel_launch
// contains ONLY kernel launches (graph-capture safe, no host API calls).

// Scratch: interleaved fp16 volumes (uint2 = half4 per voxel)
__device__ uint2 g_v0[32 * 32 * 32];
__device__ uint2 g_v1[64 * 64 * 64];
__device__ uint2 g_v2[128 * 128 * 128];
__device__ uint2 g_v3[256 * 256 * 256];

template<int NVOX>
__device__ __forceinline__ void transpose_body(const float* __restrict__ src,
                                               uint2* __restrict__ dst)
{
    int idx = blockIdx.x * blockDim.x + threadIdx.x;
    if (idx >= NVOX) return;
    float c0 = __ldg(src + 0 * NVOX + idx);
    float c1 = __ldg(src + 1 * NVOX + idx);
    float c2 = __ldg(src + 2 * NVOX + idx);
    float c3 = __ldg(src + 3 * NVOX + idx);
    __half2 lo = __floats2half2_rn(c0, c1);
    __half2 hi = __floats2half2_rn(c2, c3);
    uint2 v;
    v.x = *reinterpret_cast<unsigned*>(&lo);
    v.y = *reinterpret_cast<unsigned*>(&hi);
    dst[idx] = v;
}

__global__ void __launch_bounds__(256)
transpose_v0(const float* __restrict__ src) { transpose_body<32 * 32 * 32>(src, g_v0); }
__global__ void __launch_bounds__(256)
transpose_v1(const float* __restrict__ src) { transpose_body<64 * 64 * 64>(src, g_v1); }
__global__ void __launch_bounds__(256)
transpose_v2(const float* __restrict__ src) { transpose_body<128 * 128 * 128>(src, g_v2); }
__global__ void __launch_bounds__(256)
transpose_v3(const float* __restrict__ src) { transpose_body<256 * 256 * 256>(src, g_v3); }

__device__ __forceinline__ float4 h4_to_f4(uint2 q)
{
    __half2 a = *reinterpret_cast<__half2*>(&q.x);
    __half2 b = *reinterpret_cast<__half2*>(&q.y);
    float2 fa = __half22float2(a);
    float2 fb = __half22float2(b);
    return make_float4(fa.x, fa.y, fb.x, fb.y);
}

__device__ __forceinline__ float4 lerp4(float4 a, float4 b, float t)
{
    return make_float4(fmaf(b.x - a.x, t, a.x),
                       fmaf(b.y - a.y, t, a.y),
                       fmaf(b.z - a.z, t, a.z),
                       fmaf(b.w - a.w, t, a.w));
}

template<int D, int H, int W>
__device__ __forceinline__ float4 sample_vol(const uint2* __restrict__ vol,
                                             float gx, float gy, float gz)
{
    // align_corners=True mapping with border clamp
    float x = fminf(fmaxf((gx + 1.0f) * (0.5f * (float)(W - 1)), 0.0f), (float)(W - 1));
    float y = fminf(fmaxf((gy + 1.0f) * (0.5f * (float)(H - 1)), 0.0f), (float)(H - 1));
    float z = fminf(fmaxf((gz + 1.0f) * (0.5f * (float)(D - 1)), 0.0f), (float)(D - 1));

    float x0f = floorf(x), y0f = floorf(y), z0f = floorf(z);
    float tx = x - x0f, ty = y - y0f, tz = z - z0f;

    // smoothstep
    tx = tx * tx * (3.0f - 2.0f * tx);
    ty = ty * ty * (3.0f - 2.0f * ty);
    tz = tz * tz * (3.0f - 2.0f * tz);

    int x0 = (int)x0f, y0 = (int)y0f, z0 = (int)z0f;
    // clamped +1 neighbors folded into (voxel-unit) address deltas
    int dx = (x0 < W - 1) ? 1     : 0;
    int dy = (y0 < H - 1) ? W     : 0;
    int dz = (z0 < D - 1) ? H * W : 0;

    int base = (z0 * H + y0) * W + x0;

    // 8 corner loads, 8B each (all 4 channels), issued back-to-back for MLP
    uint2 q000 = __ldg(vol + base);
    uint2 q001 = __ldg(vol + base + dx);
    uint2 q010 = __ldg(vol + base + dy);
    uint2 q011 = __ldg(vol + base + dy + dx);
    uint2 q100 = __ldg(vol + base + dz);
    uint2 q101 = __ldg(vol + base + dz + dx);
    uint2 q110 = __ldg(vol + base + dz + dy);
    uint2 q111 = __ldg(vol + base + dz + dy + dx);

    float4 c00 = lerp4(h4_to_f4(q000), h4_to_f4(q001), tx);
    float4 c01 = lerp4(h4_to_f4(q010), h4_to_f4(q011), tx);
    float4 c10 = lerp4(h4_to_f4(q100), h4_to_f4(q101), tx);
    float4 c11 = lerp4(h4_to_f4(q110), h4_to_f4(q111), tx);

    float4 c0 = lerp4(c00, c01, ty);
    float4 c1 = lerp4(c10, c11, ty);
    return lerp4(c0, c1, tz);
}

__global__ void __launch_bounds__(256)
multigrid_kernel(const float* __restrict__ grid,
                 float* __restrict__ out,
                 int N)
{
    int i = blockIdx.x * blockDim.x + threadIdx.x;
    if (i >= N) return;

    float gx = __ldg(grid + 3 * i + 0);
    float gy = __ldg(grid + 3 * i + 1);
    float gz = __ldg(grid + 3 * i + 2);

    float4 r0 = sample_vol< 32,  32,  32>(g_v0, gx, gy, gz);
    float4 r1 = sample_vol< 64,  64,  64>(g_v1, gx, gy, gz);
    float4 r2 = sample_vol<128, 128, 128>(g_v2, gx, gy, gz);
    float4 r3 = sample_vol<256, 256, 256>(g_v3, gx, gy, gz);

    out[ 0 * N + i] = r0.x;  out[ 1 * N + i] = r0.y;
    out[ 2 * N + i] = r0.z;  out[ 3 * N + i] = r0.w;
    out[ 4 * N + i] = r1.x;  out[ 5 * N + i] = r1.y;
    out[ 6 * N + i] = r1.z;  out[ 7 * N + i] = r1.w;
    out[ 8 * N + i] = r2.x;  out[ 9 * N + i] = r2.y;
    out[10 * N + i] = r2.z;  out[11 * N + i] = r2.w;
    out[12 * N + i] = r3.x;  out[13 * N + i] = r3.y;
    out[14 * N + i] = r3.z;  out[15 * N + i] = r3.w;
}

extern "C" void kernel_launch(void* const* d_in, const int* in_sizes, int n_in,
                              void* d_out, int out_size)
{
    const float* grid = (const float*)d_in[0];
    const float* v0   = (const float*)d_in[1];
    const float* v1   = (const float*)d_in[2];
    const float* v2   = (const float*)d_in[3];
    const float* v3   = (const float*)d_in[4];
    float* out        = (float*)d_out;

    int N = in_sizes[0] / 3;

    constexpr int NV0 = 32 * 32 * 32;
    constexpr int NV1 = 64 * 64 * 64;
    constexpr int NV2 = 128 * 128 * 128;
    constexpr int NV3 = 256 * 256 * 256;

    const int T = 256;
    transpose_v0<<<(NV0 + T - 1) / T, T>>>(v0);
    transpose_v1<<<(NV1 + T - 1) / T, T>>>(v1);
    transpose_v2<<<(NV2 + T - 1) / T, T>>>(v2);
    transpose_v3<<<(NV3 + T - 1) / T, T>>>(v3);

    multigrid_kernel<<<(N + T - 1) / T, T>>>(grid, out, N);
}

// round 11
// speedup vs baseline: 2.4671x; 1.0226x over previous
#include <cuda_runtime.h>
#include <cuda_fp16.h>

// MultiGrid multires trilinear sampling, smoothstep weights, align_corners.
//
// Sample kernel is L1tex wavefront-bound (scatter-gathers). Dual-alignment
// paired storage for v0..v2: store each small volume twice as half4-voxel
// pairs -- copy A natural, copy B shifted by one voxel -- so the (x0, x0+1)
// corner pair is ONE aligned 16B load for any x0 parity. 4 loads/vol instead
// of 8. v3 stays single-copy (duplication costs more transpose DRAM + L2
// residency than it saves in wavefronts).
//
//   g_vXa : copy A, uint4 j covers voxels (2j,   2j+1)   [x0 even]
//   g_vXb : copy B, uint4 j covers voxels (2j+1, 2j+2)   [x0 odd]
//   For voxel v of matching parity the uint4 index is v>>1 in either copy.
//   Copy B's final half-slot is never written (zero-init device global);
//   it is reachable only when tx == 0, so its weight is exactly zero.

#define NV0 (32 * 32 * 32)
#define NV1 (64 * 64 * 64)
#define NV2 (128 * 128 * 128)
#define NV3 (256 * 256 * 256)

__device__ uint4 g_v0a[NV0 / 2];
__device__ uint4 g_v0b[NV0 / 2];
__device__ uint4 g_v1a[NV1 / 2];
__device__ uint4 g_v1b[NV1 / 2];
__device__ uint4 g_v2a[NV2 / 2];
__device__ uint4 g_v2b[NV2 / 2];
__device__ uint2 g_v3[NV3];

// ---- transpose: [4,D,H,W] fp32 -> [D,H,W,4] fp16 (+ shifted copy B) ----

__device__ __forceinline__ uint2 pack_h4(float c0, float c1, float c2, float c3)
{
    __half2 lo = __floats2half2_rn(c0, c1);
    __half2 hi = __floats2half2_rn(c2, c3);
    uint2 v;
    v.x = *reinterpret_cast<unsigned*>(&lo);
    v.y = *reinterpret_cast<unsigned*>(&hi);
    return v;
}

template<int NVOX>
__device__ __forceinline__ void transpose_dual_body(const float* __restrict__ src,
                                                    uint2* __restrict__ dstA,
                                                    uint2* __restrict__ dstB)
{
    int idx = blockIdx.x * blockDim.x + threadIdx.x;
    if (idx >= NVOX) return;
    float c0 = __ldg(src + 0 * NVOX + idx);
    float c1 = __ldg(src + 1 * NVOX + idx);
    float c2 = __ldg(src + 2 * NVOX + idx);
    float c3 = __ldg(src + 3 * NVOX + idx);
    uint2 v = pack_h4(c0, c1, c2, c3);
    dstA[idx] = v;                          // A[v] = vol[v]
    if (idx + 1 < NVOX) {
        // B[v] = vol[v+1]  (written by the thread owning vol[v+1])
    }
    if (idx > 0) dstB[idx - 1] = v;         // B[v-1] = vol[v]
}

__global__ void __launch_bounds__(256)
transpose_v0(const float* __restrict__ src)
{ transpose_dual_body<NV0>(src, (uint2*)g_v0a, (uint2*)g_v0b); }

__global__ void __launch_bounds__(256)
transpose_v1(const float* __restrict__ src)
{ transpose_dual_body<NV1>(src, (uint2*)g_v1a, (uint2*)g_v1b); }

__global__ void __launch_bounds__(256)
transpose_v2(const float* __restrict__ src)
{ transpose_dual_body<NV2>(src, (uint2*)g_v2a, (uint2*)g_v2b); }

// v3: 2 voxels per thread, float2 channel loads, one uint4 store
__global__ void __launch_bounds__(256)
transpose_v3(const float* __restrict__ src)
{
    int p = blockIdx.x * blockDim.x + threadIdx.x;   // voxel-pair index
    if (p >= NV3 / 2) return;
    const float2* s0 = (const float2*)(src + 0 * NV3);
    const float2* s1 = (const float2*)(src + 1 * NV3);
    const float2* s2 = (const float2*)(src + 2 * NV3);
    const float2* s3 = (const float2*)(src + 3 * NV3);
    float2 a = __ldg(s0 + p);
    float2 b = __ldg(s1 + p);
    float2 c = __ldg(s2 + p);
    float2 d = __ldg(s3 + p);
    uint2 v0 = pack_h4(a.x, b.x, c.x, d.x);
    uint2 v1 = pack_h4(a.y, b.y, c.y, d.y);
    uint4 q;
    q.x = v0.x; q.y = v0.y; q.z = v1.x; q.w = v1.y;
    ((uint4*)g_v3)[p] = q;
}

// ---- sampling ----

__device__ __forceinline__ float4 h4_to_f4(unsigned lo, unsigned hi)
{
    __half2 a = *reinterpret_cast<__half2*>(&lo);
    __half2 b = *reinterpret_cast<__half2*>(&hi);
    float2 fa = __half22float2(a);
    float2 fb = __half22float2(b);
    return make_float4(fa.x, fa.y, fb.x, fb.y);
}

__device__ __forceinline__ float4 lerp4(float4 a, float4 b, float t)
{
    return make_float4(fmaf(b.x - a.x, t, a.x),
                       fmaf(b.y - a.y, t, a.y),
                       fmaf(b.z - a.z, t, a.z),
                       fmaf(b.w - a.w, t, a.w));
}

struct Coord {
    int k;        // voxel index of corner 000
    int ky, kz;   // clamped y/z neighbor deltas (voxel units, even)
    int odd;      // x0 parity
    float tx, ty, tz;
};

template<int D, int H, int W>
__device__ __forceinline__ Coord make_coord(float gx, float gy, float gz)
{
    float x = fminf(fmaxf((gx + 1.0f) * (0.5f * (float)(W - 1)), 0.0f), (float)(W - 1));
    float y = fminf(fmaxf((gy + 1.0f) * (0.5f * (float)(H - 1)), 0.0f), (float)(H - 1));
    float z = fminf(fmaxf((gz + 1.0f) * (0.5f * (float)(D - 1)), 0.0f), (float)(D - 1));

    float x0f = floorf(x), y0f = floorf(y), z0f = floorf(z);
    float tx = x - x0f, ty = y - y0f, tz = z - z0f;

    // smoothstep
    tx = tx * tx * (3.0f - 2.0f * tx);
    ty = ty * ty * (3.0f - 2.0f * ty);
    tz = tz * tz * (3.0f - 2.0f * tz);

    int x0 = (int)x0f, y0 = (int)y0f, z0 = (int)z0f;

    Coord c;
    c.odd = x0 & 1;
    c.k   = (z0 * H + y0) * W + x0;
    c.ky  = (y0 < H - 1) ? W     : 0;
    c.kz  = (z0 < D - 1) ? H * W : 0;
    c.tx = tx; c.ty = ty; c.tz = tz;
    return c;
}

// paired-copy sampling: 4 x LDG.128, each = both x corners of one (y,z) row
template<int D, int H, int W>
__device__ __forceinline__ float4 sample_paired(const uint4* __restrict__ A,
                                                const uint4* __restrict__ B,
                                                float gx, float gy, float gz)
{
    Coord c = make_coord<D, H, W>(gx, gy, gz);
    const uint4* P = c.odd ? B : A;
    int k  = c.k  >> 1;           // ky/kz even -> shifts commute with >>1
    int ky = c.ky >> 1;
    int kz = c.kz >> 1;

    uint4 q00 = __ldg(P + k);
    uint4 q01 = __ldg(P + k + ky);
    uint4 q10 = __ldg(P + k + kz);
    uint4 q11 = __ldg(P + k + kz + ky);

    float4 c00 = lerp4(h4_to_f4(q00.x, q00.y), h4_to_f4(q00.z, q00.w), c.tx);
    float4 c01 = lerp4(h4_to_f4(q01.x, q01.y), h4_to_f4(q01.z, q01.w), c.tx);
    float4 c10 = lerp4(h4_to_f4(q10.x, q10.y), h4_to_f4(q10.z, q10.w), c.tx);
    float4 c11 = lerp4(h4_to_f4(q11.x, q11.y), h4_to_f4(q11.z, q11.w), c.tx);

    float4 c0 = lerp4(c00, c01, c.ty);
    float4 c1 = lerp4(c10, c11, c.ty);
    return lerp4(c0, c1, c.tz);
}

// single-copy sampling (v3): 8 x LDG.64
template<int D, int H, int W>
__device__ __forceinline__ float4 sample_single(const uint2* __restrict__ vol,
                                                float gx, float gy, float gz)
{
    Coord c = make_coord<D, H, W>(gx, gy, gz);
    int dx = ((c.k % W) < W - 1) ? 1 : 0;   // x-clamp fold

    uint2 q000 = __ldg(vol + c.k);
    uint2 q001 = __ldg(vol + c.k + dx);
    uint2 q010 = __ldg(vol + c.k + c.ky);
    uint2 q011 = __ldg(vol + c.k + c.ky + dx);
    uint2 q100 = __ldg(vol + c.k + c.kz);
    uint2 q101 = __ldg(vol + c.k + c.kz + dx);
    uint2 q110 = __ldg(vol + c.k + c.kz + c.ky);
    uint2 q111 = __ldg(vol + c.k + c.kz + c.ky + dx);

    float4 c00 = lerp4(h4_to_f4(q000.x, q000.y), h4_to_f4(q001.x, q001.y), c.tx);
    float4 c01 = lerp4(h4_to_f4(q010.x, q010.y), h4_to_f4(q011.x, q011.y), c.tx);
    float4 c10 = lerp4(h4_to_f4(q100.x, q100.y), h4_to_f4(q101.x, q101.y), c.tx);
    float4 c11 = lerp4(h4_to_f4(q110.x, q110.y), h4_to_f4(q111.x, q111.y), c.tx);

    float4 c0 = lerp4(c00, c01, c.ty);
    float4 c1 = lerp4(c10, c11, c.ty);
    return lerp4(c0, c1, c.tz);
}

__global__ void __launch_bounds__(256)
multigrid_kernel(const float* __restrict__ grid,
                 float* __restrict__ out,
                 int N)
{
    int i = blockIdx.x * blockDim.x + threadIdx.x;
    if (i >= N) return;

    float gx = __ldg(grid + 3 * i + 0);
    float gy = __ldg(grid + 3 * i + 1);
    float gz = __ldg(grid + 3 * i + 2);

    float4 r0 = sample_paired< 32,  32,  32>(g_v0a, g_v0b, gx, gy, gz);
    float4 r1 = sample_paired< 64,  64,  64>(g_v1a, g_v1b, gx, gy, gz);
    float4 r2 = sample_paired<128, 128, 128>(g_v2a, g_v2b, gx, gy, gz);
    float4 r3 = sample_single<256, 256, 256>(g_v3, gx, gy, gz);

    out[ 0 * N + i] = r0.x;  out[ 1 * N + i] = r0.y;
    out[ 2 * N + i] = r0.z;  out[ 3 * N + i] = r0.w;
    out[ 4 * N + i] = r1.x;  out[ 5 * N + i] = r1.y;
    out[ 6 * N + i] = r1.z;  out[ 7 * N + i] = r1.w;
    out[ 8 * N + i] = r2.x;  out[ 9 * N + i] = r2.y;
    out[10 * N + i] = r2.z;  out[11 * N + i] = r2.w;
    out[12 * N + i] = r3.x;  out[13 * N + i] = r3.y;
    out[14 * N + i] = r3.z;  out[15 * N + i] = r3.w;
}

extern "C" void kernel_launch(void* const* d_in, const int* in_sizes, int n_in,
                              void* d_out, int out_size)
{
    const float* grid = (const float*)d_in[0];
    const float* v0   = (const float*)d_in[1];
    const float* v1   = (const float*)d_in[2];
    const float* v2   = (const float*)d_in[3];
    const float* v3   = (const float*)d_in[4];
    float* out        = (float*)d_out;

    int N = in_sizes[0] / 3;

    const int T = 256;
    transpose_v0<<<(NV0 + T - 1) / T, T>>>(v0);
    transpose_v1<<<(NV1 + T - 1) / T, T>>>(v1);
    transpose_v2<<<(NV2 + T - 1) / T, T>>>(v2);
    transpose_v3<<<(NV3 / 2 + T - 1) / T, T>>>(v3);

    multigrid_kernel<<<(N + T - 1) / T, T>>>(grid, out, N);
}